// round 15
// baseline (speedup 1.0000x reference)
#include <cuda_runtime.h>
#include <math.h>
#include <float.h>

#define NB   8
#define CIN  888
#define HW   1024
#define EC   66
#define DC   64

// ---------------- scratch (device globals; no allocation allowed) ----------
__device__ float g_x64  [NB*DC*HW];
__device__ float g_xsh  [NB*EC*HW];
__device__ float g_xf2  [NB*EC*HW];
__device__ float g_out64[NB*DC*HW];
__device__ float g_tmp2 [NB*DC*HW];
__device__ float g_feat [NB*6*HW];

__device__ __forceinline__ unsigned f2tf32(float f){
    unsigned u;
    asm("cvt.rna.tf32.f32 %0, %1;" : "=r"(u) : "f"(f));
    return u;
}

// ---------------- K1: 1x1 conv via TF32 mma.sync, 32px x 64oc blocks,
//                  grid 256 (2 blocks/SM), tf32 stored in smem, mean/max in
//                  registers at load time ----------------------------------
__global__ __launch_bounds__(256) void k_gemm(const float* __restrict__ x,
                                              const float* __restrict__ W,
                                              const float* __restrict__ bias)
{
    __shared__ unsigned Xs[2][32][25];
    __shared__ unsigned Ws[2][64][25];
    __shared__ float redS[8][32];
    __shared__ float redM[8][32];

    const int n  = blockIdx.y;
    const int p0 = blockIdx.x * 32;
    const int t  = threadIdx.x;
    const int w    = t >> 5;
    const int lane = t & 31;
    const int lg   = lane >> 2;
    const int lk   = lane & 3;
    const int mrow0 = (w & 3) * 16;    // oc base (4 m-positions)
    const int ncol0 = (w >> 2) * 16;   // px base (2 n-positions)
    const float* xn = x + (size_t)n*CIN*HW + p0;

    float psum = 0.f, pmax = -FLT_MAX;  // for px = t&31 over k-subset t>>5 (+8i)
    float c[2][4];
#pragma unroll
    for (int ni=0;ni<2;ni++)
#pragma unroll
        for (int k=0;k<4;k++) c[ni][k]=0.f;

    // preload chunk 0
#pragma unroll
    for (int i=0;i<3;i++){
        const int e=t+i*256, kk=e>>5, px=e&31;
        const float v = xn[kk*HW+px];
        psum += v; pmax = fmaxf(pmax, v);
        Xs[0][px][kk] = f2tf32(v);
    }
#pragma unroll
    for (int i=0;i<6;i++){
        const int e=t+i*256, oc=e/24, kk=e-oc*24;
        Ws[0][oc][kk] = f2tf32(W[oc*CIN+kk]);
    }
    __syncthreads();

    for (int ch=0; ch<37; ch++){
        const int cur = ch & 1;
        if (ch < 36){
            const int k0 = (ch+1)*24;
            const int nxt = cur ^ 1;
#pragma unroll
            for (int i=0;i<3;i++){
                const int e=t+i*256, kk=e>>5, px=e&31;
                const float v = xn[(k0+kk)*HW+px];
                psum += v; pmax = fmaxf(pmax, v);
                Xs[nxt][px][kk] = f2tf32(v);
            }
#pragma unroll
            for (int i=0;i<6;i++){
                const int e=t+i*256, oc=e/24, kk=e-oc*24;
                Ws[nxt][oc][kk] = f2tf32(W[oc*CIN+k0+kk]);
            }
        }
#pragma unroll
        for (int ks=0; ks<3; ks++){
            const int kb = ks*8;
            unsigned a[4], b[2][2];
            const int r = mrow0 + lg;
            a[0] = Ws[cur][r  ][kb+lk  ];
            a[1] = Ws[cur][r+8][kb+lk  ];
            a[2] = Ws[cur][r  ][kb+lk+4];
            a[3] = Ws[cur][r+8][kb+lk+4];
#pragma unroll
            for (int ni=0;ni<2;ni++){
                const int cpx = ncol0 + ni*8 + lg;
                b[ni][0] = Xs[cur][cpx][kb+lk  ];
                b[ni][1] = Xs[cur][cpx][kb+lk+4];
            }
#pragma unroll
            for (int ni=0;ni<2;ni++){
                asm volatile(
                    "mma.sync.aligned.m16n8k8.row.col.f32.tf32.tf32.f32 "
                    "{%0,%1,%2,%3}, {%4,%5,%6,%7}, {%8,%9}, {%0,%1,%2,%3};"
                    : "+f"(c[ni][0]),"+f"(c[ni][1]),"+f"(c[ni][2]),"+f"(c[ni][3])
                    : "r"(a[0]),"r"(a[1]),"r"(a[2]),"r"(a[3]),
                      "r"(b[ni][0]),"r"(b[ni][1]));
            }
        }
        __syncthreads();
    }

    // mean/max final reduce (8 k-groups x 32 px)
    redS[t>>5][t&31] = psum;
    redM[t>>5][t&31] = pmax;
    __syncthreads();
    if (t < 32){
        float s = 0.f, m = -FLT_MAX;
#pragma unroll
        for (int g=0; g<8; g++){ s += redS[g][t]; m = fmaxf(m, redM[g][t]); }
        const int p = p0 + t;
        g_xsh[((size_t)n*EC+43)*HW + p] = s * (1.f/888.f);  // mean -> shuffled ch43
        g_xsh[((size_t)n*EC+65)*HW + p] = m;                 // max  -> shuffled ch65
    }

    // epilogue: bias + scatter (direct + shuffled)
#pragma unroll
    for (int half=0; half<2; half++){
        const int oc = mrow0 + lg + half*8;
        const float bb = __ldg(&bias[oc]);
        const int sc = (oc%3)*22 + oc/3;
        float* d1 = &g_x64[((size_t)n*DC+oc)*HW];
        float* d2 = &g_xsh[((size_t)n*EC+sc)*HW];
#pragma unroll
        for (int ni=0;ni<2;ni++){
            const int col = ncol0 + ni*8 + lk*2;
            const float v0 = c[ni][half*2+0] + bb;
            const float v1 = c[ni][half*2+1] + bb;
            d1[p0+col]   = v0; d1[p0+col+1] = v1;
            d2[p0+col]   = v0; d2[p0+col+1] = v1;
        }
    }
}

// ---------------- K2: multi-scale depthwise (3/5/7) + depthwise-3 pos-enc
//                  residual, fused per channel -----------------------------
__global__ __launch_bounds__(256) void k_branch_pe(
    const float* __restrict__ W3,const float* __restrict__ b3,
    const float* __restrict__ W5,const float* __restrict__ b5,
    const float* __restrict__ W7,const float* __restrict__ b7,
    const float* __restrict__ Wpe,const float* __restrict__ bpe)
{
    __shared__ float s0[38*38];
    __shared__ float s1[32*33];
    __shared__ float wsm[64];
    const int ch = blockIdx.x, n = blockIdx.y;
    const int t = threadIdx.x;
    int r; const float* Wb; float bb;
    if (ch < 22)      { r=1; Wb=W3+ch*9;       bb=b3[ch];    }
    else if (ch < 44) { r=2; Wb=W5+(ch-22)*25; bb=b5[ch-22]; }
    else              { r=3; Wb=W7+(ch-44)*49; bb=b7[ch-44]; }
    const int kw = 2*r+1, nw = kw*kw;
    if (t < nw) wsm[t] = Wb[t];
    if (t >= 49 && t < 58) wsm[t] = Wpe[ch*9 + t-49];
    const float bpev = bpe[ch];
    const float* in = g_xsh + ((size_t)n*EC+ch)*HW;
    for (int e=t; e<38*38; e+=256){
        const int sy = e/38 - 3, sx = e%38 - 3;
        s0[e] = (sy>=0 && sy<32 && sx>=0 && sx<32) ? in[sy*32+sx] : 0.f;
    }
    __syncthreads();
#pragma unroll
    for (int q=0;q<4;q++){
        const int p = t + q*256; const int y=p>>5, xx=p&31;
        float a = bb;
        for (int dy=-r; dy<=r; dy++)
            for (int dx=-r; dx<=r; dx++)
                a += wsm[(dy+r)*kw + dx+r] * s0[(y+3+dy)*38 + xx+3+dx];
        s1[y*33+xx] = a;
    }
    __syncthreads();
    float* out = g_xf2 + ((size_t)n*EC+ch)*HW;
#pragma unroll
    for (int q=0;q<4;q++){
        const int p = t + q*256; const int y=p>>5, xx=p&31;
        float a = bpev;
#pragma unroll
        for (int dy=-1; dy<=1; dy++){
            const int yy=y+dy;
#pragma unroll
            for (int dx=-1; dx<=1; dx++){
                const int xc=xx+dx;
                const float v = (yy>=0&&yy<32&&xc>=0&&xc<32) ? s1[yy*33+xc] : 0.f;
                a += wsm[49+(dy+1)*3+dx+1] * v;
            }
        }
        out[p] = s1[y*33+xx] + a;
    }
}

// ---------------- K3: LayerNorm(channels) + 3x3 conv 66->64 via TF32 mma +
//                  GELU + residual(x64) -------------------------------------
__global__ __launch_bounds__(256) void k_mainconv(
    const float* __restrict__ lng, const float* __restrict__ lnb,
    const float* __restrict__ Wlast, const float* __restrict__ blast)
{
    __shared__ float sLn[72][4][36];
    __shared__ float sA[64][25];
    __shared__ float sg[EC], sb[EC];

    const int n  = blockIdx.y;
    const int ty = blockIdx.x;
    const int t  = threadIdx.x;
    const int w    = t >> 5;
    const int lane = t & 31;
    const int lg   = lane >> 2;
    const int lk   = lane & 3;
    const int mrow0 = (w & 1) * 32;
    const int ncol0 = (w >> 1) * 16;

    if (t < EC){ sg[t]=lng[t]; sb[t]=lnb[t]; }
    for (int e=t; e<6*4*36; e+=256){
        const int cc=e/(4*36), rem=e%(4*36);
        sLn[66+cc][rem/36][rem%36] = 0.f;
    }
    for (int e=t; e<EC*136; e+=256){
        const int cch=e/136, rem=e%136, rr=rem/34, cc=rem%34;
        const int gy = 2*ty-1+rr, gx = cc-1;
        sLn[cch][rr][cc] = (gy>=0&&gy<32&&gx>=0&&gx<32) ?
            g_xf2[((size_t)n*EC+cch)*HW + gy*32+gx] : 0.f;
    }
    __syncthreads();
    if (t < 136){
        const int rr=t/34, cc=t%34;
        const int gy=2*ty-1+rr, gx=cc-1;
        if (gy>=0&&gy<32&&gx>=0&&gx<32){
            float s=0.f, sq=0.f;
#pragma unroll
            for (int cch=0;cch<EC;cch++){ const float v=sLn[cch][rr][cc]; s+=v; sq+=v*v; }
            const float mu = s*(1.f/66.f);
            const float var = sq*(1.f/66.f) - mu*mu;
            const float rs = rsqrtf(var + 1e-5f);
#pragma unroll
            for (int cch=0;cch<EC;cch++)
                sLn[cch][rr][cc] = __uint_as_float(
                    f2tf32((sLn[cch][rr][cc]-mu)*rs*sg[cch]+sb[cch]));
        }
    }

    float c[2][2][4];
#pragma unroll
    for (int mi=0;mi<2;mi++)
#pragma unroll
        for (int ni=0;ni<2;ni++)
#pragma unroll
            for (int k=0;k<4;k++) c[mi][ni][k]=0.f;

    for (int ch8=0; ch8<9; ch8++){
        for (int sub=0; sub<3; sub++){
            __syncthreads();
#pragma unroll
            for (int i=0;i<6;i++){
                const int e=t+i*256;
                const int oc=e/24, kl=e%24;
                const int klc = sub*24+kl;
                const int cg = ch8*8 + klc/9, off = klc%9;
                sA[oc][kl] = (cg<EC) ?
                    __uint_as_float(f2tf32(Wlast[oc*EC*9 + cg*9 + off])) : 0.f;
            }
            __syncthreads();
#pragma unroll
            for (int ks=0; ks<3; ks++){
                const int kbl = ks*8;
                const int kbg = sub*24 + kbl;
                unsigned a[2][4];
#pragma unroll
                for (int mi=0;mi<2;mi++){
                    const int r = mrow0 + mi*16 + lg;
                    a[mi][0] = __float_as_uint(sA[r  ][kbl+lk  ]);
                    a[mi][1] = __float_as_uint(sA[r+8][kbl+lk  ]);
                    a[mi][2] = __float_as_uint(sA[r  ][kbl+lk+4]);
                    a[mi][3] = __float_as_uint(sA[r+8][kbl+lk+4]);
                }
                const int k1 = kbg+lk, k2 = kbg+lk+4;
                const int c1 = k1/9, o1 = k1-9*c1;
                const int c2 = k2/9, o2 = k2-9*c2;
                const int dy1 = o1/3, dx1 = o1-3*dy1;
                const int dy2 = o2/3, dx2 = o2-3*dy2;
                const int cg1 = ch8*8+c1, cg2 = ch8*8+c2;
                unsigned b[2][2];
#pragma unroll
                for (int ni=0;ni<2;ni++){
                    const int cpx = ncol0 + ni*8 + lg;
                    const int row = cpx>>5, col = cpx&31;
                    b[ni][0] = __float_as_uint(sLn[cg1][row+dy1][col+dx1]);
                    b[ni][1] = __float_as_uint(sLn[cg2][row+dy2][col+dx2]);
                }
#pragma unroll
                for (int mi=0;mi<2;mi++)
#pragma unroll
                    for (int ni=0;ni<2;ni++){
                        asm volatile(
                            "mma.sync.aligned.m16n8k8.row.col.f32.tf32.tf32.f32 "
                            "{%0,%1,%2,%3}, {%4,%5,%6,%7}, {%8,%9}, {%0,%1,%2,%3};"
                            : "+f"(c[mi][ni][0]),"+f"(c[mi][ni][1]),
                              "+f"(c[mi][ni][2]),"+f"(c[mi][ni][3])
                            : "r"(a[mi][0]),"r"(a[mi][1]),"r"(a[mi][2]),"r"(a[mi][3]),
                              "r"(b[ni][0]),"r"(b[ni][1]));
                    }
            }
        }
    }

#pragma unroll
    for (int mi=0;mi<2;mi++){
#pragma unroll
        for (int half=0; half<2; half++){
            const int oc = mrow0 + mi*16 + lg + half*8;
            const float bb = __ldg(&blast[oc]);
            const float* xr  = g_x64  + ((size_t)n*DC+oc)*HW;
            float*       out = g_out64 + ((size_t)n*DC+oc)*HW;
#pragma unroll
            for (int ni=0;ni<2;ni++){
                const int colt = ncol0 + ni*8 + lk*2;
#pragma unroll
                for (int u=0;u<2;u++){
                    const int px = colt+u;
                    const int p = (2*ty + (px>>5))*32 + (px&31);
                    const float v = c[mi][ni][half*2+u] + bb;
                    const float ge = 0.5f*v*(1.f+erff(v*0.70710678118654752f));
                    out[p] = ge + xr[p];
                }
            }
        }
    }
}

// ---------------- K4: aux head dw3 -> dw5(dilation 3), fused per channel ---
__global__ __launch_bounds__(256) void k_aux(const float* __restrict__ Wa0,
                                             const float* __restrict__ Was)
{
    __shared__ float s0[34*34];
    __shared__ float s1[32*33];
    __shared__ float wsm[40];
    const int ch = blockIdx.x, n = blockIdx.y;
    const int t = threadIdx.x;
    if (t < 9)              wsm[t] = Wa0[ch*9+t];
    if (t >= 9 && t < 34)   wsm[t] = Was[ch*25 + t-9];
    const float* in = g_out64 + ((size_t)n*DC+ch)*HW;
    for (int e=t; e<34*34; e+=256){
        const int sy=e/34-1, sx=e%34-1;
        s0[e] = (sy>=0&&sy<32&&sx>=0&&sx<32)? in[sy*32+sx] : 0.f;
    }
    __syncthreads();
#pragma unroll
    for (int q=0;q<4;q++){
        const int p=t+q*256, y=p>>5, xx=p&31;
        float a=0.f;
#pragma unroll
        for (int dy=0;dy<3;dy++)
#pragma unroll
            for (int dx=0;dx<3;dx++)
                a += wsm[dy*3+dx]*s0[(y+dy)*34 + xx+dx];
        s1[y*33+xx]=a;
    }
    __syncthreads();
    float* out = g_tmp2 + ((size_t)n*DC+ch)*HW;
#pragma unroll
    for (int q=0;q<4;q++){
        const int p=t+q*256, y=p>>5, xx=p&31;
        float a=0.f;
#pragma unroll
        for (int ky=0;ky<5;ky++){
            const int yy = y + (ky-2)*3;
            if (yy<0||yy>=32) continue;
#pragma unroll
            for (int kx=0;kx<5;kx++){
                const int xc = xx + (kx-2)*3;
                if (xc<0||xc>=32) continue;
                a += wsm[9+ky*5+kx]*s1[yy*33+xc];
            }
        }
        out[p]=a;
    }
}

// ---------------- K5: 1x1 conv 64->6 ---------------------------------------
__global__ __launch_bounds__(256) void k_pw(const float* __restrict__ Wout)
{
    __shared__ float w[6*64];
    const int t = threadIdx.x;
    for (int i=t; i<384; i+=256) w[i] = Wout[i];
    __syncthreads();
    const int gp = blockIdx.x*256+t;
    const int n = gp>>10, p = gp&1023;
    const float* tp = g_tmp2 + (size_t)n*DC*HW + p;
    float acc[6]={0.f,0.f,0.f,0.f,0.f,0.f};
    for (int oc=0;oc<64;oc++){
        const float v = tp[(size_t)oc*HW];
#pragma unroll
        for (int k=0;k<6;k++) acc[k] += w[k*64+oc]*v;
    }
    float* f = g_feat + (size_t)n*6*HW + p;
#pragma unroll
    for (int k=0;k<6;k++) f[(size_t)k*HW] = acc[k];
}

// ---------------- K6: bilinear 32x32 -> 1024x1024 (half-pixel, clamped) ----
__global__ __launch_bounds__(256) void k_upsample(float* __restrict__ out)
{
    const int idx = blockIdx.x*256 + threadIdx.x;
    const int ox4 = idx & 255;
    const int oy  = (idx >> 8) & 1023;
    const int nk  = idx >> 18;
    if (nk >= NB*6) return;
    const float* f = g_feat + (size_t)nk*HW;

    const float sy = (oy + 0.5f)*0.03125f - 0.5f;
    const float fy = floorf(sy);
    const float wy = sy - fy;
    const int   iy = (int)fy;
    const int   y0 = min(max(iy,0),31);
    const int   y1 = min(iy+1,31);

    const int   ox0 = ox4*4;
    const float sx  = (ox0 + 0.5f)*0.03125f - 0.5f;
    const float fx  = floorf(sx);
    const float wx0 = sx - fx;
    const int   ix  = (int)fx;
    const int   x0  = min(max(ix,0),31);
    const int   x1  = min(ix+1,31);

    const float v00 = f[y0*32+x0], v01 = f[y0*32+x1];
    const float v10 = f[y1*32+x0], v11 = f[y1*32+x1];
    const float a = v00 + (v10-v00)*wy;
    const float b = v01 + (v11-v01)*wy;
    const float d = b - a;
    float4 o;
    o.x = a + d*wx0;
    o.y = a + d*(wx0+0.03125f);
    o.z = a + d*(wx0+0.0625f);
    o.w = a + d*(wx0+0.09375f);
    __stcs(&reinterpret_cast<float4*>(out)[idx], o);
}

// ---------------- launch ----------------------------------------------------
extern "C" void kernel_launch(void* const* d_in, const int* in_sizes, int n_in,
                              void* d_out, int out_size)
{
    (void)out_size;
    const float *x=0,*W1=0,*b1=0,*W3=0,*b3=0,*W5=0,*b5=0,*W7=0,*b7=0;
    const float *Wpe=0,*bpe=0,*lng=0,*lnb=0,*Wlast=0,*blast=0,*Wa0=0,*Was=0,*Wout=0;
    int c22=0, c64=0, c66=0;
    for (int i=0;i<n_in;i++){
        const int s = in_sizes[i];
        const float* p = (const float*)d_in[i];
        switch (s){
            case 7274496: x=p; break;
            case 56832:   W1=p; break;
            case 198:     W3=p; break;
            case 550:     W5=p; break;
            case 1078:    W7=p; break;
            case 594:     Wpe=p; break;
            case 38016:   Wlast=p; break;
            case 576:     Wa0=p; break;
            case 1600:    Was=p; break;
            case 384:     Wout=p; break;
            case 64:      if (c64==0) b1=p; else blast=p; c64++; break;
            case 22:      if (c22==0) b3=p; else if (c22==1) b5=p; else b7=p; c22++; break;
            case 66:      if (c66==0) bpe=p; else if (c66==1) lng=p; else lnb=p; c66++; break;
            default: break; // h, w scalars
        }
    }

    k_gemm     <<<dim3(32,NB), 256>>>(x, W1, b1);
    k_branch_pe<<<dim3(EC,NB), 256>>>(W3,b3,W5,b5,W7,b7,Wpe,bpe);
    k_mainconv <<<dim3(16,NB), 256>>>(lng,lnb,Wlast,blast);
    k_aux      <<<dim3(DC,NB), 256>>>(Wa0,Was);
    k_pw       <<<32, 256>>>(Wout);
    k_upsample <<<(NB*6*1024*256)/256, 256>>>((float*)d_out);
}

// round 16
// speedup vs baseline: 1.1514x; 1.1514x over previous
#include <cuda_runtime.h>
#include <math.h>
#include <float.h>

#define NB   8
#define CIN  888
#define HW   1024
#define EC   66
#define DC   64

// ---------------- scratch (device globals; no allocation allowed) ----------
__device__ float g_x64  [NB*DC*HW];
__device__ float g_xsh  [NB*EC*HW];
__device__ float g_xf2  [NB*EC*HW];
__device__ float g_out64[NB*DC*HW];
__device__ float g_tmp2 [NB*DC*HW];
__device__ float g_feat [NB*6*HW];

__device__ __forceinline__ unsigned f2tf32(float f){
    unsigned u;
    asm("cvt.rna.tf32.f32 %0, %1;" : "=r"(u) : "f"(f));
    return u;
}

__device__ __forceinline__ void cpa4(void* s, const void* g){
    unsigned a = (unsigned)__cvta_generic_to_shared(s);
    asm volatile("cp.async.ca.shared.global [%0], [%1], 4;" :: "r"(a), "l"(g));
}
#define CP_COMMIT() asm volatile("cp.async.commit_group;")
#define CP_WAIT0()  asm volatile("cp.async.wait_group 0;")

// ---------------- K1: 1x1 conv via TF32 mma.sync (64oc x 64px x 888k) +
//                  mean/max + shuffle scatter; cp.async double buffer -------
__global__ __launch_bounds__(256) void k_gemm(const float* __restrict__ x,
                                              const float* __restrict__ W,
                                              const float* __restrict__ bias)
{
    __shared__ float Xs[2][64][25];
    __shared__ float Ws[2][64][25];
    __shared__ float redS[4][64];
    __shared__ float redM[4][64];

    const int n  = blockIdx.y;
    const int p0 = blockIdx.x * 64;
    const int t  = threadIdx.x;
    const int w    = t >> 5;
    const int lane = t & 31;
    const int lg   = lane >> 2;
    const int lk   = lane & 3;
    const int mrow0 = (w & 1) * 32;
    const int ncol0 = (w >> 1) * 16;
    const float* xn = x + (size_t)n*CIN*HW + p0;

    const int rpx = t & 63, rkg = t >> 6;
    float psum = 0.f, pmax = -FLT_MAX;

    float c[2][2][4];
#pragma unroll
    for (int mi=0;mi<2;mi++)
#pragma unroll
        for (int ni=0;ni<2;ni++)
#pragma unroll
            for (int k=0;k<4;k++) c[mi][ni][k]=0.f;

    // indices for this thread's 12 async copies per chunk
    const int xkk[6] = { (t+0*256)>>6, (t+1*256)>>6, (t+2*256)>>6,
                         (t+3*256)>>6, (t+4*256)>>6, (t+5*256)>>6 };
    const int xpx = t & 63;
    int woc[6], wkk[6];
#pragma unroll
    for (int i=0;i<6;i++){ int e=t+i*256; woc[i]=e/24; wkk[i]=e-woc[i]*24; }

    // preload chunk 0
#pragma unroll
    for (int i=0;i<6;i++) cpa4(&Xs[0][xpx][xkk[i]], &xn[xkk[i]*HW+xpx]);
#pragma unroll
    for (int i=0;i<6;i++) cpa4(&Ws[0][woc[i]][wkk[i]], &W[woc[i]*CIN+wkk[i]]);
    CP_COMMIT();
    CP_WAIT0();
    __syncthreads();

    for (int ch=0; ch<37; ch++){
        const int cur = ch & 1;
        if (ch < 36){
            const int k0 = (ch+1)*24;
            const int nxt = cur ^ 1;
#pragma unroll
            for (int i=0;i<6;i++) cpa4(&Xs[nxt][xpx][xkk[i]], &xn[(k0+xkk[i])*HW+xpx]);
#pragma unroll
            for (int i=0;i<6;i++) cpa4(&Ws[nxt][woc[i]][wkk[i]], &W[woc[i]*CIN+k0+wkk[i]]);
            CP_COMMIT();
        }
        // mean/max partials on current X tile (smem)
#pragma unroll
        for (int k=0;k<6;k++){
            const float v = Xs[cur][rpx][rkg*6+k];
            psum += v;
            pmax = fmaxf(pmax, v);
        }
        // 3 k-steps of 8
#pragma unroll
        for (int ks=0; ks<3; ks++){
            const int kb = ks*8;
            unsigned a[2][4], b[2][2];
#pragma unroll
            for (int mi=0;mi<2;mi++){
                const int r = mrow0 + mi*16 + lg;
                a[mi][0] = f2tf32(Ws[cur][r  ][kb+lk  ]);
                a[mi][1] = f2tf32(Ws[cur][r+8][kb+lk  ]);
                a[mi][2] = f2tf32(Ws[cur][r  ][kb+lk+4]);
                a[mi][3] = f2tf32(Ws[cur][r+8][kb+lk+4]);
            }
#pragma unroll
            for (int ni=0;ni<2;ni++){
                const int cpx = ncol0 + ni*8 + lg;
                b[ni][0] = f2tf32(Xs[cur][cpx][kb+lk  ]);
                b[ni][1] = f2tf32(Xs[cur][cpx][kb+lk+4]);
            }
#pragma unroll
            for (int mi=0;mi<2;mi++)
#pragma unroll
                for (int ni=0;ni<2;ni++){
                    asm volatile(
                        "mma.sync.aligned.m16n8k8.row.col.f32.tf32.tf32.f32 "
                        "{%0,%1,%2,%3}, {%4,%5,%6,%7}, {%8,%9}, {%0,%1,%2,%3};"
                        : "+f"(c[mi][ni][0]),"+f"(c[mi][ni][1]),
                          "+f"(c[mi][ni][2]),"+f"(c[mi][ni][3])
                        : "r"(a[mi][0]),"r"(a[mi][1]),"r"(a[mi][2]),"r"(a[mi][3]),
                          "r"(b[ni][0]),"r"(b[ni][1]));
                }
        }
        if (ch < 36) CP_WAIT0();
        __syncthreads();
    }

    redS[rkg][rpx] = psum;
    redM[rkg][rpx] = pmax;
    __syncthreads();
    if (t < 64){
        const float s = redS[0][t]+redS[1][t]+redS[2][t]+redS[3][t];
        const float m = fmaxf(fmaxf(redM[0][t],redM[1][t]),
                              fmaxf(redM[2][t],redM[3][t]));
        const int p = p0 + t;
        g_xsh[((size_t)n*EC+43)*HW + p] = s * (1.f/888.f);
        g_xsh[((size_t)n*EC+65)*HW + p] = m;
    }

#pragma unroll
    for (int mi=0;mi<2;mi++){
#pragma unroll
        for (int half=0; half<2; half++){
            const int oc = mrow0 + mi*16 + lg + half*8;
            const float bb = __ldg(&bias[oc]);
            const int sc = (oc%3)*22 + oc/3;
            float* d1 = &g_x64[((size_t)n*DC+oc)*HW];
            float* d2 = &g_xsh[((size_t)n*EC+sc)*HW];
#pragma unroll
            for (int ni=0;ni<2;ni++){
                const int col = ncol0 + ni*8 + lk*2;
                const float v0 = c[mi][ni][half*2+0] + bb;
                const float v1 = c[mi][ni][half*2+1] + bb;
                d1[p0+col]   = v0; d1[p0+col+1] = v1;
                d2[p0+col]   = v0; d2[p0+col+1] = v1;
            }
        }
    }
}

// ---------------- K2: multi-scale depthwise (3/5/7) + depthwise-3 pos-enc
//                  residual, fused per channel -----------------------------
__global__ __launch_bounds__(256) void k_branch_pe(
    const float* __restrict__ W3,const float* __restrict__ b3,
    const float* __restrict__ W5,const float* __restrict__ b5,
    const float* __restrict__ W7,const float* __restrict__ b7,
    const float* __restrict__ Wpe,const float* __restrict__ bpe)
{
    __shared__ float s0[38*38];
    __shared__ float s1[32*33];
    __shared__ float wsm[64];
    const int ch = blockIdx.x, n = blockIdx.y;
    const int t = threadIdx.x;
    int r; const float* Wb; float bb;
    if (ch < 22)      { r=1; Wb=W3+ch*9;       bb=b3[ch];    }
    else if (ch < 44) { r=2; Wb=W5+(ch-22)*25; bb=b5[ch-22]; }
    else              { r=3; Wb=W7+(ch-44)*49; bb=b7[ch-44]; }
    const int kw = 2*r+1, nw = kw*kw;
    if (t < nw) wsm[t] = Wb[t];
    if (t >= 49 && t < 58) wsm[t] = Wpe[ch*9 + t-49];
    const float bpev = bpe[ch];
    const float* in = g_xsh + ((size_t)n*EC+ch)*HW;
    for (int e=t; e<38*38; e+=256){
        const int sy = e/38 - 3, sx = e%38 - 3;
        s0[e] = (sy>=0 && sy<32 && sx>=0 && sx<32) ? in[sy*32+sx] : 0.f;
    }
    __syncthreads();
#pragma unroll
    for (int q=0;q<4;q++){
        const int p = t + q*256; const int y=p>>5, xx=p&31;
        float a = bb;
        for (int dy=-r; dy<=r; dy++)
            for (int dx=-r; dx<=r; dx++)
                a += wsm[(dy+r)*kw + dx+r] * s0[(y+3+dy)*38 + xx+3+dx];
        s1[y*33+xx] = a;
    }
    __syncthreads();
    float* out = g_xf2 + ((size_t)n*EC+ch)*HW;
#pragma unroll
    for (int q=0;q<4;q++){
        const int p = t + q*256; const int y=p>>5, xx=p&31;
        float a = bpev;
#pragma unroll
        for (int dy=-1; dy<=1; dy++){
            const int yy=y+dy;
#pragma unroll
            for (int dx=-1; dx<=1; dx++){
                const int xc=xx+dx;
                const float v = (yy>=0&&yy<32&&xc>=0&&xc<32) ? s1[yy*33+xc] : 0.f;
                a += wsm[49+(dy+1)*3+dx+1] * v;
            }
        }
        out[p] = s1[y*33+xx] + a;
    }
}

// ---------------- K3: LayerNorm(channels) + 3x3 conv 66->64 via TF32 mma +
//                  GELU + residual(x64) -------------------------------------
__global__ __launch_bounds__(256) void k_mainconv(
    const float* __restrict__ lng, const float* __restrict__ lnb,
    const float* __restrict__ Wlast, const float* __restrict__ blast)
{
    __shared__ float sLn[72][4][36];
    __shared__ float sA[64][25];
    __shared__ float sg[EC], sb[EC];

    const int n  = blockIdx.y;
    const int ty = blockIdx.x;
    const int t  = threadIdx.x;
    const int w    = t >> 5;
    const int lane = t & 31;
    const int lg   = lane >> 2;
    const int lk   = lane & 3;
    const int mrow0 = (w & 1) * 32;
    const int ncol0 = (w >> 1) * 16;

    if (t < EC){ sg[t]=lng[t]; sb[t]=lnb[t]; }
    for (int e=t; e<6*4*36; e+=256){
        const int cc=e/(4*36), rem=e%(4*36);
        sLn[66+cc][rem/36][rem%36] = 0.f;
    }
    for (int e=t; e<EC*136; e+=256){
        const int cch=e/136, rem=e%136, rr=rem/34, cc=rem%34;
        const int gy = 2*ty-1+rr, gx = cc-1;
        sLn[cch][rr][cc] = (gy>=0&&gy<32&&gx>=0&&gx<32) ?
            g_xf2[((size_t)n*EC+cch)*HW + gy*32+gx] : 0.f;
    }
    __syncthreads();
    if (t < 136){
        const int rr=t/34, cc=t%34;
        const int gy=2*ty-1+rr, gx=cc-1;
        if (gy>=0&&gy<32&&gx>=0&&gx<32){
            float s=0.f, sq=0.f;
#pragma unroll
            for (int cch=0;cch<EC;cch++){ const float v=sLn[cch][rr][cc]; s+=v; sq+=v*v; }
            const float mu = s*(1.f/66.f);
            const float var = sq*(1.f/66.f) - mu*mu;
            const float rs = rsqrtf(var + 1e-5f);
#pragma unroll
            for (int cch=0;cch<EC;cch++)
                sLn[cch][rr][cc] = __uint_as_float(
                    f2tf32((sLn[cch][rr][cc]-mu)*rs*sg[cch]+sb[cch]));
        }
    }

    float c[2][2][4];
#pragma unroll
    for (int mi=0;mi<2;mi++)
#pragma unroll
        for (int ni=0;ni<2;ni++)
#pragma unroll
            for (int k=0;k<4;k++) c[mi][ni][k]=0.f;

    for (int ch8=0; ch8<9; ch8++){
        for (int sub=0; sub<3; sub++){
            __syncthreads();
#pragma unroll
            for (int i=0;i<6;i++){
                const int e=t+i*256;
                const int oc=e/24, kl=e%24;
                const int klc = sub*24+kl;
                const int cg = ch8*8 + klc/9, off = klc%9;
                sA[oc][kl] = (cg<EC) ?
                    __uint_as_float(f2tf32(Wlast[oc*EC*9 + cg*9 + off])) : 0.f;
            }
            __syncthreads();
#pragma unroll
            for (int ks=0; ks<3; ks++){
                const int kbl = ks*8;
                const int kbg = sub*24 + kbl;
                unsigned a[2][4];
#pragma unroll
                for (int mi=0;mi<2;mi++){
                    const int r = mrow0 + mi*16 + lg;
                    a[mi][0] = __float_as_uint(sA[r  ][kbl+lk  ]);
                    a[mi][1] = __float_as_uint(sA[r+8][kbl+lk  ]);
                    a[mi][2] = __float_as_uint(sA[r  ][kbl+lk+4]);
                    a[mi][3] = __float_as_uint(sA[r+8][kbl+lk+4]);
                }
                const int k1 = kbg+lk, k2 = kbg+lk+4;
                const int c1 = k1/9, o1 = k1-9*c1;
                const int c2 = k2/9, o2 = k2-9*c2;
                const int dy1 = o1/3, dx1 = o1-3*dy1;
                const int dy2 = o2/3, dx2 = o2-3*dy2;
                const int cg1 = ch8*8+c1, cg2 = ch8*8+c2;
                unsigned b[2][2];
#pragma unroll
                for (int ni=0;ni<2;ni++){
                    const int cpx = ncol0 + ni*8 + lg;
                    const int row = cpx>>5, col = cpx&31;
                    b[ni][0] = __float_as_uint(sLn[cg1][row+dy1][col+dx1]);
                    b[ni][1] = __float_as_uint(sLn[cg2][row+dy2][col+dx2]);
                }
#pragma unroll
                for (int mi=0;mi<2;mi++)
#pragma unroll
                    for (int ni=0;ni<2;ni++){
                        asm volatile(
                            "mma.sync.aligned.m16n8k8.row.col.f32.tf32.tf32.f32 "
                            "{%0,%1,%2,%3}, {%4,%5,%6,%7}, {%8,%9}, {%0,%1,%2,%3};"
                            : "+f"(c[mi][ni][0]),"+f"(c[mi][ni][1]),
                              "+f"(c[mi][ni][2]),"+f"(c[mi][ni][3])
                            : "r"(a[mi][0]),"r"(a[mi][1]),"r"(a[mi][2]),"r"(a[mi][3]),
                              "r"(b[ni][0]),"r"(b[ni][1]));
                    }
            }
        }
    }

#pragma unroll
    for (int mi=0;mi<2;mi++){
#pragma unroll
        for (int half=0; half<2; half++){
            const int oc = mrow0 + mi*16 + lg + half*8;
            const float bb = __ldg(&blast[oc]);
            const float* xr  = g_x64  + ((size_t)n*DC+oc)*HW;
            float*       out = g_out64 + ((size_t)n*DC+oc)*HW;
#pragma unroll
            for (int ni=0;ni<2;ni++){
                const int colt = ncol0 + ni*8 + lk*2;
#pragma unroll
                for (int u=0;u<2;u++){
                    const int px = colt+u;
                    const int p = (2*ty + (px>>5))*32 + (px&31);
                    const float v = c[mi][ni][half*2+u] + bb;
                    const float ge = 0.5f*v*(1.f+erff(v*0.70710678118654752f));
                    out[p] = ge + xr[p];
                }
            }
        }
    }
}

// ---------------- K4: aux head dw3 -> dw5(dilation 3), fused per channel ---
__global__ __launch_bounds__(256) void k_aux(const float* __restrict__ Wa0,
                                             const float* __restrict__ Was)
{
    __shared__ float s0[34*34];
    __shared__ float s1[32*33];
    __shared__ float wsm[40];
    const int ch = blockIdx.x, n = blockIdx.y;
    const int t = threadIdx.x;
    if (t < 9)              wsm[t] = Wa0[ch*9+t];
    if (t >= 9 && t < 34)   wsm[t] = Was[ch*25 + t-9];
    const float* in = g_out64 + ((size_t)n*DC+ch)*HW;
    for (int e=t; e<34*34; e+=256){
        const int sy=e/34-1, sx=e%34-1;
        s0[e] = (sy>=0&&sy<32&&sx>=0&&sx<32)? in[sy*32+sx] : 0.f;
    }
    __syncthreads();
#pragma unroll
    for (int q=0;q<4;q++){
        const int p=t+q*256, y=p>>5, xx=p&31;
        float a=0.f;
#pragma unroll
        for (int dy=0;dy<3;dy++)
#pragma unroll
            for (int dx=0;dx<3;dx++)
                a += wsm[dy*3+dx]*s0[(y+dy)*34 + xx+dx];
        s1[y*33+xx]=a;
    }
    __syncthreads();
    float* out = g_tmp2 + ((size_t)n*DC+ch)*HW;
#pragma unroll
    for (int q=0;q<4;q++){
        const int p=t+q*256, y=p>>5, xx=p&31;
        float a=0.f;
#pragma unroll
        for (int ky=0;ky<5;ky++){
            const int yy = y + (ky-2)*3;
            if (yy<0||yy>=32) continue;
#pragma unroll
            for (int kx=0;kx<5;kx++){
                const int xc = xx + (kx-2)*3;
                if (xc<0||xc>=32) continue;
                a += wsm[9+ky*5+kx]*s1[yy*33+xc];
            }
        }
        out[p]=a;
    }
}

// ---------------- K5: 1x1 conv 64->6 ---------------------------------------
__global__ __launch_bounds__(128) void k_pw(const float* __restrict__ Wout)
{
    __shared__ float w[6*64];
    const int t = threadIdx.x;
    for (int i=t; i<384; i+=128) w[i] = Wout[i];
    __syncthreads();
    const int gp = blockIdx.x*128+t;
    const int n = gp>>10, p = gp&1023;
    const float* tp = g_tmp2 + (size_t)n*DC*HW + p;
    float acc[6]={0.f,0.f,0.f,0.f,0.f,0.f};
    for (int oc=0;oc<64;oc++){
        const float v = tp[(size_t)oc*HW];
#pragma unroll
        for (int k=0;k<6;k++) acc[k] += w[k*64+oc]*v;
    }
    float* f = g_feat + (size_t)n*6*HW + p;
#pragma unroll
    for (int k=0;k<6;k++) f[(size_t)k*HW] = acc[k];
}

// ---------------- K6: bilinear 32x32 -> 1024x1024 (half-pixel, clamped) ----
__global__ __launch_bounds__(256) void k_upsample(float* __restrict__ out)
{
    const int idx = blockIdx.x*256 + threadIdx.x;
    const int ox4 = idx & 255;
    const int oy  = (idx >> 8) & 1023;
    const int nk  = idx >> 18;
    if (nk >= NB*6) return;
    const float* f = g_feat + (size_t)nk*HW;

    const float sy = (oy + 0.5f)*0.03125f - 0.5f;
    const float fy = floorf(sy);
    const float wy = sy - fy;
    const int   iy = (int)fy;
    const int   y0 = min(max(iy,0),31);
    const int   y1 = min(iy+1,31);

    const int   ox0 = ox4*4;
    const float sx  = (ox0 + 0.5f)*0.03125f - 0.5f;
    const float fx  = floorf(sx);
    const float wx0 = sx - fx;
    const int   ix  = (int)fx;
    const int   x0  = min(max(ix,0),31);
    const int   x1  = min(ix+1,31);

    const float v00 = f[y0*32+x0], v01 = f[y0*32+x1];
    const float v10 = f[y1*32+x0], v11 = f[y1*32+x1];
    const float a = v00 + (v10-v00)*wy;
    const float b = v01 + (v11-v01)*wy;
    const float d = b - a;
    float4 o;
    o.x = a + d*wx0;
    o.y = a + d*(wx0+0.03125f);
    o.z = a + d*(wx0+0.0625f);
    o.w = a + d*(wx0+0.09375f);
    __stcs(&reinterpret_cast<float4*>(out)[idx], o);
}

// ---------------- launch ----------------------------------------------------
extern "C" void kernel_launch(void* const* d_in, const int* in_sizes, int n_in,
                              void* d_out, int out_size)
{
    (void)out_size;
    const float *x=0,*W1=0,*b1=0,*W3=0,*b3=0,*W5=0,*b5=0,*W7=0,*b7=0;
    const float *Wpe=0,*bpe=0,*lng=0,*lnb=0,*Wlast=0,*blast=0,*Wa0=0,*Was=0,*Wout=0;
    int c22=0, c64=0, c66=0;
    for (int i=0;i<n_in;i++){
        const int s = in_sizes[i];
        const float* p = (const float*)d_in[i];
        switch (s){
            case 7274496: x=p; break;
            case 56832:   W1=p; break;
            case 198:     W3=p; break;
            case 550:     W5=p; break;
            case 1078:    W7=p; break;
            case 594:     Wpe=p; break;
            case 38016:   Wlast=p; break;
            case 576:     Wa0=p; break;
            case 1600:    Was=p; break;
            case 384:     Wout=p; break;
            case 64:      if (c64==0) b1=p; else blast=p; c64++; break;
            case 22:      if (c22==0) b3=p; else if (c22==1) b5=p; else b7=p; c22++; break;
            case 66:      if (c66==0) bpe=p; else if (c66==1) lng=p; else lnb=p; c66++; break;
            default: break; // h, w scalars
        }
    }

    k_gemm     <<<dim3(16,NB), 256>>>(x, W1, b1);
    k_branch_pe<<<dim3(EC,NB), 256>>>(W3,b3,W5,b5,W7,b7,Wpe,bpe);
    k_mainconv <<<dim3(16,NB), 256>>>(lng,lnb,Wlast,blast);
    k_aux      <<<dim3(DC,NB), 256>>>(Wa0,Was);
    k_pw       <<<64, 128>>>(Wout);
    k_upsample <<<(NB*6*1024*256)/256, 256>>>((float*)d_out);
}

// round 17
// speedup vs baseline: 1.2211x; 1.0606x over previous
#include <cuda_runtime.h>
#include <math.h>
#include <float.h>

#define NB   8
#define CIN  888
#define HW   1024
#define EC   66
#define DC   64

// ---------------- scratch (device globals; no allocation allowed) ----------
__device__ float g_x64  [NB*DC*HW];
__device__ float g_xsh  [NB*EC*HW];
__device__ float g_xf2  [NB*EC*HW];
__device__ float g_out64[NB*DC*HW];
__device__ float g_tmp2 [NB*DC*HW];
__device__ float g_feat [NB*6*HW];

__device__ __forceinline__ unsigned f2tf32(float f){
    unsigned u;
    asm("cvt.rna.tf32.f32 %0, %1;" : "=r"(u) : "f"(f));
    return u;
}

__device__ __forceinline__ void cpa16(void* s, const void* g){
    unsigned a = (unsigned)__cvta_generic_to_shared(s);
    asm volatile("cp.async.cg.shared.global [%0], [%1], 16;" :: "r"(a), "l"(g));
}
#define CP_COMMIT() asm volatile("cp.async.commit_group;")
#define CP_WAIT0()  asm volatile("cp.async.wait_group 0;")

// ---------------- K1: 1x1 conv via TF32 mma.sync (64oc x 64px x 888k),
//                  512 thr, 16B cp.async, conflict-free smem ----------------
// Xs k-major [24][72]: B-frag bank = 8*lk+lg (unique); 16B-aligned stride.
// Ws oc-major [64][28]: A-frag bank = -4*lg+lk (unique); 16B-aligned stride.
__global__ __launch_bounds__(512) void k_gemm(const float* __restrict__ x,
                                              const float* __restrict__ W,
                                              const float* __restrict__ bias)
{
    __shared__ __align__(16) float Xs[2][24][72];
    __shared__ __align__(16) float Ws[2][64][28];
    __shared__ float redS[8][64];
    __shared__ float redM[8][64];

    const int n  = blockIdx.y;
    const int p0 = blockIdx.x * 64;
    const int t  = threadIdx.x;
    const int w    = t >> 5;          // 0..15
    const int lane = t & 31;
    const int lg   = lane >> 2;       // 0..7
    const int lk   = lane & 3;        // 0..3
    const int mrow0 = (w & 3) * 16;   // oc base
    const int ncol0 = (w >> 2) * 16;  // px base
    const float* xn = x + (size_t)n*CIN*HW + p0;

    const int rpx = t & 63, rkg = t >> 6;      // mean/max: px, k-group (0..7)
    float psum = 0.f, pmax = -FLT_MAX;

    float c[2][4];
#pragma unroll
    for (int ni=0;ni<2;ni++)
#pragma unroll
        for (int k=0;k<4;k++) c[ni][k]=0.f;

    // copy indices (t < 384 does one X float4 and one W float4)
    const int xkk = t >> 4, xp4 = (t & 15) * 4;     // X: kk 0..23, px4
    const int woc = t / 6,  wq4 = (t - 6*(t/6)) * 4; // W: oc 0..63, k offset

    if (t < 384){
        cpa16(&Xs[0][xkk][xp4], &xn[xkk*HW + xp4]);
        cpa16(&Ws[0][woc][wq4], &W[woc*CIN + wq4]);
    }
    CP_COMMIT();
    CP_WAIT0();
    __syncthreads();

    for (int ch=0; ch<37; ch++){
        const int cur = ch & 1;
        if (ch < 36){
            const int k0 = (ch+1)*24;
            const int nxt = cur ^ 1;
            if (t < 384){
                cpa16(&Xs[nxt][xkk][xp4], &xn[(k0+xkk)*HW + xp4]);
                cpa16(&Ws[nxt][woc][wq4], &W[woc*CIN + k0 + wq4]);
            }
            CP_COMMIT();
        }
        // mean/max partials (3 k per chunk per thread)
#pragma unroll
        for (int k=0;k<3;k++){
            const float v = Xs[cur][rkg*3+k][rpx];
            psum += v;
            pmax = fmaxf(pmax, v);
        }
        // 3 k-steps of 8; each warp: m16 x n16
#pragma unroll
        for (int ks=0; ks<3; ks++){
            const int kb = ks*8;
            unsigned a[4], b[2][2];
            const int r = mrow0 + lg;
            a[0] = f2tf32(Ws[cur][r  ][kb+lk  ]);
            a[1] = f2tf32(Ws[cur][r+8][kb+lk  ]);
            a[2] = f2tf32(Ws[cur][r  ][kb+lk+4]);
            a[3] = f2tf32(Ws[cur][r+8][kb+lk+4]);
#pragma unroll
            for (int ni=0;ni<2;ni++){
                const int cpx = ncol0 + ni*8 + lg;
                b[ni][0] = f2tf32(Xs[cur][kb+lk  ][cpx]);
                b[ni][1] = f2tf32(Xs[cur][kb+lk+4][cpx]);
            }
#pragma unroll
            for (int ni=0;ni<2;ni++){
                asm volatile(
                    "mma.sync.aligned.m16n8k8.row.col.f32.tf32.tf32.f32 "
                    "{%0,%1,%2,%3}, {%4,%5,%6,%7}, {%8,%9}, {%0,%1,%2,%3};"
                    : "+f"(c[ni][0]),"+f"(c[ni][1]),"+f"(c[ni][2]),"+f"(c[ni][3])
                    : "r"(a[0]),"r"(a[1]),"r"(a[2]),"r"(a[3]),
                      "r"(b[ni][0]),"r"(b[ni][1]));
            }
        }
        if (ch < 36) CP_WAIT0();
        __syncthreads();
    }

    // mean/max final reduce
    redS[rkg][rpx] = psum;
    redM[rkg][rpx] = pmax;
    __syncthreads();
    if (t < 64){
        float s = 0.f, m = -FLT_MAX;
#pragma unroll
        for (int g=0; g<8; g++){ s += redS[g][t]; m = fmaxf(m, redM[g][t]); }
        const int p = p0 + t;
        g_xsh[((size_t)n*EC+43)*HW + p] = s * (1.f/888.f);  // mean -> shuffled ch43
        g_xsh[((size_t)n*EC+65)*HW + p] = m;                 // max  -> shuffled ch65
    }

    // epilogue: bias + scatter (direct + shuffled)
#pragma unroll
    for (int half=0; half<2; half++){
        const int oc = mrow0 + lg + half*8;
        const float bb = __ldg(&bias[oc]);
        const int sc = (oc%3)*22 + oc/3;
        float* d1 = &g_x64[((size_t)n*DC+oc)*HW];
        float* d2 = &g_xsh[((size_t)n*EC+sc)*HW];
#pragma unroll
        for (int ni=0;ni<2;ni++){
            const int col = ncol0 + ni*8 + lk*2;
            const float v0 = c[ni][half*2+0] + bb;
            const float v1 = c[ni][half*2+1] + bb;
            d1[p0+col]   = v0; d1[p0+col+1] = v1;
            d2[p0+col]   = v0; d2[p0+col+1] = v1;
        }
    }
}

// ---------------- K2: multi-scale depthwise (3/5/7) + depthwise-3 pos-enc
//                  residual, fused per channel -----------------------------
__global__ __launch_bounds__(256) void k_branch_pe(
    const float* __restrict__ W3,const float* __restrict__ b3,
    const float* __restrict__ W5,const float* __restrict__ b5,
    const float* __restrict__ W7,const float* __restrict__ b7,
    const float* __restrict__ Wpe,const float* __restrict__ bpe)
{
    __shared__ float s0[38*38];
    __shared__ float s1[32*33];
    __shared__ float wsm[64];
    const int ch = blockIdx.x, n = blockIdx.y;
    const int t = threadIdx.x;
    int r; const float* Wb; float bb;
    if (ch < 22)      { r=1; Wb=W3+ch*9;       bb=b3[ch];    }
    else if (ch < 44) { r=2; Wb=W5+(ch-22)*25; bb=b5[ch-22]; }
    else              { r=3; Wb=W7+(ch-44)*49; bb=b7[ch-44]; }
    const int kw = 2*r+1, nw = kw*kw;
    if (t < nw) wsm[t] = Wb[t];
    if (t >= 49 && t < 58) wsm[t] = Wpe[ch*9 + t-49];
    const float bpev = bpe[ch];
    const float* in = g_xsh + ((size_t)n*EC+ch)*HW;
    for (int e=t; e<38*38; e+=256){
        const int sy = e/38 - 3, sx = e%38 - 3;
        s0[e] = (sy>=0 && sy<32 && sx>=0 && sx<32) ? in[sy*32+sx] : 0.f;
    }
    __syncthreads();
#pragma unroll
    for (int q=0;q<4;q++){
        const int p = t + q*256; const int y=p>>5, xx=p&31;
        float a = bb;
        for (int dy=-r; dy<=r; dy++)
            for (int dx=-r; dx<=r; dx++)
                a += wsm[(dy+r)*kw + dx+r] * s0[(y+3+dy)*38 + xx+3+dx];
        s1[y*33+xx] = a;
    }
    __syncthreads();
    float* out = g_xf2 + ((size_t)n*EC+ch)*HW;
#pragma unroll
    for (int q=0;q<4;q++){
        const int p = t + q*256; const int y=p>>5, xx=p&31;
        float a = bpev;
#pragma unroll
        for (int dy=-1; dy<=1; dy++){
            const int yy=y+dy;
#pragma unroll
            for (int dx=-1; dx<=1; dx++){
                const int xc=xx+dx;
                const float v = (yy>=0&&yy<32&&xc>=0&&xc<32) ? s1[yy*33+xc] : 0.f;
                a += wsm[49+(dy+1)*3+dx+1] * v;
            }
        }
        out[p] = s1[y*33+xx] + a;
    }
}

// ---------------- K3: LayerNorm(channels) + 3x3 conv 66->64 via TF32 mma +
//                  GELU + residual(x64) -------------------------------------
__global__ __launch_bounds__(256) void k_mainconv(
    const float* __restrict__ lng, const float* __restrict__ lnb,
    const float* __restrict__ Wlast, const float* __restrict__ blast)
{
    __shared__ float sLn[72][4][36];
    __shared__ float sA[64][25];
    __shared__ float sg[EC], sb[EC];

    const int n  = blockIdx.y;
    const int ty = blockIdx.x;
    const int t  = threadIdx.x;
    const int w    = t >> 5;
    const int lane = t & 31;
    const int lg   = lane >> 2;
    const int lk   = lane & 3;
    const int mrow0 = (w & 1) * 32;
    const int ncol0 = (w >> 1) * 16;

    if (t < EC){ sg[t]=lng[t]; sb[t]=lnb[t]; }
    for (int e=t; e<6*4*36; e+=256){
        const int cc=e/(4*36), rem=e%(4*36);
        sLn[66+cc][rem/36][rem%36] = 0.f;
    }
    for (int e=t; e<EC*136; e+=256){
        const int cch=e/136, rem=e%136, rr=rem/34, cc=rem%34;
        const int gy = 2*ty-1+rr, gx = cc-1;
        sLn[cch][rr][cc] = (gy>=0&&gy<32&&gx>=0&&gx<32) ?
            g_xf2[((size_t)n*EC+cch)*HW + gy*32+gx] : 0.f;
    }
    __syncthreads();
    if (t < 136){
        const int rr=t/34, cc=t%34;
        const int gy=2*ty-1+rr, gx=cc-1;
        if (gy>=0&&gy<32&&gx>=0&&gx<32){
            float s=0.f, sq=0.f;
#pragma unroll
            for (int cch=0;cch<EC;cch++){ const float v=sLn[cch][rr][cc]; s+=v; sq+=v*v; }
            const float mu = s*(1.f/66.f);
            const float var = sq*(1.f/66.f) - mu*mu;
            const float rs = rsqrtf(var + 1e-5f);
#pragma unroll
            for (int cch=0;cch<EC;cch++)
                sLn[cch][rr][cc] = __uint_as_float(
                    f2tf32((sLn[cch][rr][cc]-mu)*rs*sg[cch]+sb[cch]));
        }
    }

    float c[2][2][4];
#pragma unroll
    for (int mi=0;mi<2;mi++)
#pragma unroll
        for (int ni=0;ni<2;ni++)
#pragma unroll
            for (int k=0;k<4;k++) c[mi][ni][k]=0.f;

    for (int ch8=0; ch8<9; ch8++){
        for (int sub=0; sub<3; sub++){
            __syncthreads();
#pragma unroll
            for (int i=0;i<6;i++){
                const int e=t+i*256;
                const int oc=e/24, kl=e%24;
                const int klc = sub*24+kl;
                const int cg = ch8*8 + klc/9, off = klc%9;
                sA[oc][kl] = (cg<EC) ?
                    __uint_as_float(f2tf32(Wlast[oc*EC*9 + cg*9 + off])) : 0.f;
            }
            __syncthreads();
#pragma unroll
            for (int ks=0; ks<3; ks++){
                const int kbl = ks*8;
                const int kbg = sub*24 + kbl;
                unsigned a[2][4];
#pragma unroll
                for (int mi=0;mi<2;mi++){
                    const int r = mrow0 + mi*16 + lg;
                    a[mi][0] = __float_as_uint(sA[r  ][kbl+lk  ]);
                    a[mi][1] = __float_as_uint(sA[r+8][kbl+lk  ]);
                    a[mi][2] = __float_as_uint(sA[r  ][kbl+lk+4]);
                    a[mi][3] = __float_as_uint(sA[r+8][kbl+lk+4]);
                }
                const int k1 = kbg+lk, k2 = kbg+lk+4;
                const int c1 = k1/9, o1 = k1-9*c1;
                const int c2 = k2/9, o2 = k2-9*c2;
                const int dy1 = o1/3, dx1 = o1-3*dy1;
                const int dy2 = o2/3, dx2 = o2-3*dy2;
                const int cg1 = ch8*8+c1, cg2 = ch8*8+c2;
                unsigned b[2][2];
#pragma unroll
                for (int ni=0;ni<2;ni++){
                    const int cpx = ncol0 + ni*8 + lg;
                    const int row = cpx>>5, col = cpx&31;
                    b[ni][0] = __float_as_uint(sLn[cg1][row+dy1][col+dx1]);
                    b[ni][1] = __float_as_uint(sLn[cg2][row+dy2][col+dx2]);
                }
#pragma unroll
                for (int mi=0;mi<2;mi++)
#pragma unroll
                    for (int ni=0;ni<2;ni++){
                        asm volatile(
                            "mma.sync.aligned.m16n8k8.row.col.f32.tf32.tf32.f32 "
                            "{%0,%1,%2,%3}, {%4,%5,%6,%7}, {%8,%9}, {%0,%1,%2,%3};"
                            : "+f"(c[mi][ni][0]),"+f"(c[mi][ni][1]),
                              "+f"(c[mi][ni][2]),"+f"(c[mi][ni][3])
                            : "r"(a[mi][0]),"r"(a[mi][1]),"r"(a[mi][2]),"r"(a[mi][3]),
                              "r"(b[ni][0]),"r"(b[ni][1]));
                    }
            }
        }
    }

#pragma unroll
    for (int mi=0;mi<2;mi++){
#pragma unroll
        for (int half=0; half<2; half++){
            const int oc = mrow0 + mi*16 + lg + half*8;
            const float bb = __ldg(&blast[oc]);
            const float* xr  = g_x64  + ((size_t)n*DC+oc)*HW;
            float*       out = g_out64 + ((size_t)n*DC+oc)*HW;
#pragma unroll
            for (int ni=0;ni<2;ni++){
                const int colt = ncol0 + ni*8 + lk*2;
#pragma unroll
                for (int u=0;u<2;u++){
                    const int px = colt+u;
                    const int p = (2*ty + (px>>5))*32 + (px&31);
                    const float v = c[mi][ni][half*2+u] + bb;
                    const float ge = 0.5f*v*(1.f+erff(v*0.70710678118654752f));
                    out[p] = ge + xr[p];
                }
            }
        }
    }
}

// ---------------- K4: aux head dw3 -> dw5(dilation 3), fused per channel ---
__global__ __launch_bounds__(256) void k_aux(const float* __restrict__ Wa0,
                                             const float* __restrict__ Was)
{
    __shared__ float s0[34*34];
    __shared__ float s1[32*33];
    __shared__ float wsm[40];
    const int ch = blockIdx.x, n = blockIdx.y;
    const int t = threadIdx.x;
    if (t < 9)              wsm[t] = Wa0[ch*9+t];
    if (t >= 9 && t < 34)   wsm[t] = Was[ch*25 + t-9];
    const float* in = g_out64 + ((size_t)n*DC+ch)*HW;
    for (int e=t; e<34*34; e+=256){
        const int sy=e/34-1, sx=e%34-1;
        s0[e] = (sy>=0&&sy<32&&sx>=0&&sx<32)? in[sy*32+sx] : 0.f;
    }
    __syncthreads();
#pragma unroll
    for (int q=0;q<4;q++){
        const int p=t+q*256, y=p>>5, xx=p&31;
        float a=0.f;
#pragma unroll
        for (int dy=0;dy<3;dy++)
#pragma unroll
            for (int dx=0;dx<3;dx++)
                a += wsm[dy*3+dx]*s0[(y+dy)*34 + xx+dx];
        s1[y*33+xx]=a;
    }
    __syncthreads();
    float* out = g_tmp2 + ((size_t)n*DC+ch)*HW;
#pragma unroll
    for (int q=0;q<4;q++){
        const int p=t+q*256, y=p>>5, xx=p&31;
        float a=0.f;
#pragma unroll
        for (int ky=0;ky<5;ky++){
            const int yy = y + (ky-2)*3;
            if (yy<0||yy>=32) continue;
#pragma unroll
            for (int kx=0;kx<5;kx++){
                const int xc = xx + (kx-2)*3;
                if (xc<0||xc>=32) continue;
                a += wsm[9+ky*5+kx]*s1[yy*33+xc];
            }
        }
        out[p]=a;
    }
}

// ---------------- K5: 1x1 conv 64->6 ---------------------------------------
__global__ __launch_bounds__(128) void k_pw(const float* __restrict__ Wout)
{
    __shared__ float w[6*64];
    const int t = threadIdx.x;
    for (int i=t; i<384; i+=128) w[i] = Wout[i];
    __syncthreads();
    const int gp = blockIdx.x*128+t;
    const int n = gp>>10, p = gp&1023;
    const float* tp = g_tmp2 + (size_t)n*DC*HW + p;
    float acc[6]={0.f,0.f,0.f,0.f,0.f,0.f};
    for (int oc=0;oc<64;oc++){
        const float v = tp[(size_t)oc*HW];
#pragma unroll
        for (int k=0;k<6;k++) acc[k] += w[k*64+oc]*v;
    }
    float* f = g_feat + (size_t)n*6*HW + p;
#pragma unroll
    for (int k=0;k<6;k++) f[(size_t)k*HW] = acc[k];
}

// ---------------- K6: bilinear 32x32 -> 1024x1024 (half-pixel, clamped) ----
__global__ __launch_bounds__(256) void k_upsample(float* __restrict__ out)
{
    const int idx = blockIdx.x*256 + threadIdx.x;
    const int ox4 = idx & 255;
    const int oy  = (idx >> 8) & 1023;
    const int nk  = idx >> 18;
    if (nk >= NB*6) return;
    const float* f = g_feat + (size_t)nk*HW;

    const float sy = (oy + 0.5f)*0.03125f - 0.5f;
    const float fy = floorf(sy);
    const float wy = sy - fy;
    const int   iy = (int)fy;
    const int   y0 = min(max(iy,0),31);
    const int   y1 = min(iy+1,31);

    const int   ox0 = ox4*4;
    const float sx  = (ox0 + 0.5f)*0.03125f - 0.5f;
    const float fx  = floorf(sx);
    const float wx0 = sx - fx;
    const int   ix  = (int)fx;
    const int   x0  = min(max(ix,0),31);
    const int   x1  = min(ix+1,31);

    const float v00 = f[y0*32+x0], v01 = f[y0*32+x1];
    const float v10 = f[y1*32+x0], v11 = f[y1*32+x1];
    const float a = v00 + (v10-v00)*wy;
    const float b = v01 + (v11-v01)*wy;
    const float d = b - a;
    float4 o;
    o.x = a + d*wx0;
    o.y = a + d*(wx0+0.03125f);
    o.z = a + d*(wx0+0.0625f);
    o.w = a + d*(wx0+0.09375f);
    __stcs(&reinterpret_cast<float4*>(out)[idx], o);
}

// ---------------- launch ----------------------------------------------------
extern "C" void kernel_launch(void* const* d_in, const int* in_sizes, int n_in,
                              void* d_out, int out_size)
{
    (void)out_size;
    const float *x=0,*W1=0,*b1=0,*W3=0,*b3=0,*W5=0,*b5=0,*W7=0,*b7=0;
    const float *Wpe=0,*bpe=0,*lng=0,*lnb=0,*Wlast=0,*blast=0,*Wa0=0,*Was=0,*Wout=0;
    int c22=0, c64=0, c66=0;
    for (int i=0;i<n_in;i++){
        const int s = in_sizes[i];
        const float* p = (const float*)d_in[i];
        switch (s){
            case 7274496: x=p; break;
            case 56832:   W1=p; break;
            case 198:     W3=p; break;
            case 550:     W5=p; break;
            case 1078:    W7=p; break;
            case 594:     Wpe=p; break;
            case 38016:   Wlast=p; break;
            case 576:     Wa0=p; break;
            case 1600:    Was=p; break;
            case 384:     Wout=p; break;
            case 64:      if (c64==0) b1=p; else blast=p; c64++; break;
            case 22:      if (c22==0) b3=p; else if (c22==1) b5=p; else b7=p; c22++; break;
            case 66:      if (c66==0) bpe=p; else if (c66==1) lng=p; else lnb=p; c66++; break;
            default: break; // h, w scalars
        }
    }

    k_gemm     <<<dim3(16,NB), 512>>>(x, W1, b1);
    k_branch_pe<<<dim3(EC,NB), 256>>>(W3,b3,W5,b5,W7,b7,Wpe,bpe);
    k_mainconv <<<dim3(16,NB), 256>>>(lng,lnb,Wlast,blast);
    k_aux      <<<dim3(DC,NB), 256>>>(Wa0,Was);
    k_pw       <<<64, 128>>>(Wout);
    k_upsample <<<(NB*6*1024*256)/256, 256>>>((float*)d_out);
}